// round 15
// baseline (speedup 1.0000x reference)
#include <cuda_runtime.h>

#define NEGV (-1000000000.0f)
#define HTS 68    // hT row stride (transposed h: hT[k][m]); mult of 4 => 16B-aligned row quads
#define XS  132   // xl/xr row stride; mult of 4, stride%32==4 => conflict-free lane-strided LDS.128

typedef unsigned long long u64;

__device__ __forceinline__ u64 ld2(const float* p) {
    return *reinterpret_cast<const u64*>(p);
}
__device__ __forceinline__ ulonglong2 ld4(const float* p) {
    return *reinterpret_cast<const ulonglong2*>(p);
}
__device__ __forceinline__ u64 fma2(u64 a, u64 b, u64 c) {
    u64 d; asm("fma.rn.f32x2 %0,%1,%2,%3;" : "=l"(d) : "l"(a), "l"(b), "l"(c)); return d;
}
__device__ __forceinline__ u64 add2(u64 a, u64 b) {
    u64 d; asm("add.rn.f32x2 %0,%1,%2;" : "=l"(d) : "l"(a), "l"(b)); return d;
}
__device__ __forceinline__ u64 abs2(u64 a) {
    return a & 0x7FFFFFFF7FFFFFFFull;
}
__device__ __forceinline__ u64 dup2(float x) {
    u64 d; asm("mov.b64 %0,{%1,%1};" : "=l"(d) : "f"(x)); return d;
}
__device__ __forceinline__ float2 unp2(u64 a) {
    float2 r; asm("mov.b64 {%0,%1},%2;" : "=f"(r.x), "=f"(r.y) : "l"(a)); return r;
}

template<int Fout, int H, bool FINAL>
__device__ __forceinline__ void layer_body(
    float* __restrict__ hT, float* __restrict__ xln, float* __restrict__ xrn,
    float* __restrict__ eBuf, float* __restrict__ SLa, float* __restrict__ SRa,
    float* __restrict__ attS, float* __restrict__ att04S, float* __restrict__ biasS,
    float* __restrict__ scratch,  // 1024 floats: pm at [0..128H), ps at [512..512+128H)
    const float* __restrict__ impS,
    const float* __restrict__ Wl, const float* __restrict__ Wr,
    const float* __restrict__ att, const float* __restrict__ bias,
    const float* __restrict__ lng, const float* __restrict__ lnb,
    float* __restrict__ outg, int b, int tid)
{
    constexpr int C = Fout / H;

    // ---- stage att / 0.4*att / bias (read only after next sync) ----
    if (tid < Fout) {
        float a = att[tid];
        attS[tid] = a; att04S[tid] = 0.4f * a; biasS[tid] = bias[tid];
    }

    // ---- dual GEMM: xl = h @ Wl, xr = h @ Wr (adjacent-f pairs, row-quad hT broadcast) ----
    {
        constexpr int NFS   = Fout / 2;       // 64 or 32 f-pair slots per matrix
        constexpr int nGrp  = 1024 / NFS;     // 16 or 32
        constexpr int halfG = nGrp / 2;       // 8 or 16
        constexpr int rows  = 64 / halfG;     // 8 or 4
        constexpr int RP    = rows / 2;       // 4 or 2
        constexpr int RQ    = rows / 4;       // 2 or 1
        int fslot = tid % NFS;
        int grp   = tid / NFS;
        bool matSel = grp >= halfG;
        int sub     = matSel ? grp - halfG : grp;
        int rstart  = sub * rows;
        const float* W = matSel ? Wr : Wl;
        float* dst     = matSel ? xrn : xln;
        int f0 = 2 * fslot;                   // adjacent pair (f0, f0+1)
        u64 acc0[RP], acc1[RP];
        #pragma unroll
        for (int p = 0; p < RP; p++) { acc0[p] = 0ull; acc1[p] = 0ull; }
        #pragma unroll 1
        for (int kk = 0; kk < 128; kk += 8) {
            u64 wp[8];
            #pragma unroll
            for (int q = 0; q < 8; q++)
                wp[q] = ld2(&W[(kk + q) * Fout + f0]);   // LDG.64, coalesced
            #pragma unroll
            for (int q = 0; q < 8; q++) {
                float2 wv = unp2(wp[q]);
                u64 wd0 = dup2(wv.x), wd1 = dup2(wv.y);
                const float* hk = &hT[(kk + q) * HTS + rstart];
                #pragma unroll
                for (int r = 0; r < RQ; r++) {
                    ulonglong2 h4 = ld4(hk + 4 * r);     // broadcast
                    acc0[2*r]   = fma2(h4.x, wd0, acc0[2*r]);
                    acc0[2*r+1] = fma2(h4.y, wd0, acc0[2*r+1]);
                    acc1[2*r]   = fma2(h4.x, wd1, acc1[2*r]);
                    acc1[2*r+1] = fma2(h4.y, wd1, acc1[2*r+1]);
                }
            }
        }
        #pragma unroll
        for (int p = 0; p < RP; p++) {
            float2 v0 = unp2(acc0[p]), v1 = unp2(acc1[p]);
            int r = rstart + 2 * p;
            float2 s0; s0.x = v0.x; s0.y = v1.x;
            float2 s1; s1.x = v0.y; s1.y = v1.y;
            *reinterpret_cast<float2*>(&dst[r * XS + f0])       = s0;
            *reinterpret_cast<float2*>(&dst[(r + 1) * XS + f0]) = s1;
        }
    }
    __syncthreads();

    // ---- SL_i[h] = sum_c xl*att ; SR_j[h] = sum_c xr*att ----
    if (tid < 128 * H) {
        int i   = tid & 63;
        int hm  = tid >> 6;
        int h   = hm & (H - 1);
        int mat = hm / H;
        const float* x = (mat ? xrn : xln) + i * XS + h * C;
        const float* a = attS + h * C;
        u64 acc = 0ull;
        #pragma unroll
        for (int c = 0; c < C; c += 4) {
            ulonglong2 x4 = ld4(x + c);
            ulonglong2 a4 = ld4(a + c);
            acc = fma2(x4.x, a4.x, acc);
            acc = fma2(x4.y, a4.y, acc);
        }
        float2 v = unp2(acc);
        (mat ? SRa : SLa)[h * 64 + i] = v.x + v.y;
    }
    __syncthreads();

    // ---- e-phase: e_ij = 0.6*(SL_i+SR_j) + sum_c |xl+xr| * (0.4*att); mask folded ----
    {
        int l = tid & 31, w = tid >> 5;           // 32 warps
        if constexpr (!FINAL) {
            // (i-quad x h-pair) per warp: 16 quads x 4 h = 64 units / 32 warps
            int i0 = (w & 15) * 4;
            int h0 = (w >> 4) * 2;
            float impj0 = impS[l], impj1 = impS[l + 32];
            #pragma unroll 1
            for (int hh = 0; hh < 2; hh++) {
                int h = h0 + hh;
                u64 acc[4][2];
                #pragma unroll
                for (int ii = 0; ii < 4; ii++) { acc[ii][0] = 0ull; acc[ii][1] = 0ull; }
                const float* a04 = att04S + h * C;
                const float* xr0 = &xrn[l * XS + h * C];
                const float* xr1 = &xrn[(l + 32) * XS + h * C];
                const float* xlb = &xln[i0 * XS + h * C];
                #pragma unroll 2
                for (int c = 0; c < C; c += 4) {
                    ulonglong2 r0 = ld4(xr0 + c);
                    ulonglong2 r1 = ld4(xr1 + c);
                    ulonglong2 a2 = ld4(a04 + c);
                    #pragma unroll
                    for (int ii = 0; ii < 4; ii++) {
                        ulonglong2 xl4 = ld4(xlb + ii * XS + c);   // broadcast
                        acc[ii][0] = fma2(abs2(add2(xl4.x, r0.x)), a2.x, acc[ii][0]);
                        acc[ii][0] = fma2(abs2(add2(xl4.y, r0.y)), a2.y, acc[ii][0]);
                        acc[ii][1] = fma2(abs2(add2(xl4.x, r1.x)), a2.x, acc[ii][1]);
                        acc[ii][1] = fma2(abs2(add2(xl4.y, r1.y)), a2.y, acc[ii][1]);
                    }
                }
                float sr0 = SRa[h * 64 + l], sr1 = SRa[h * 64 + l + 32];
                #pragma unroll
                for (int ii = 0; ii < 4; ii++) {
                    int i = i0 + ii;
                    float impi = impS[i];
                    float sl = SLa[h * 64 + i];
                    float2 t0 = unp2(acc[ii][0]), t1 = unp2(acc[ii][1]);
                    float e0 = 0.6f * (sl + sr0) + (t0.x + t0.y);
                    float e1 = 0.6f * (sl + sr1) + (t1.x + t1.y);
                    bool ok0 = (i == l)      || (impi != 0.f && impj0 != 0.f);
                    bool ok1 = (i == l + 32) || (impi != 0.f && impj1 != 0.f);
                    eBuf[h * 4096 + i * 64 + l]      = ok0 ? e0 : NEGV;
                    eBuf[h * 4096 + i * 64 + l + 32] = ok1 ? e1 : NEGV;
                }
            }
        } else {
            // H=1, C=64: (i-quad x j-half) per warp
            int i0 = (w & 15) * 4;
            int jb = (w >> 4) * 32;
            int j  = jb + l;
            float impj = impS[j];
            u64 acc[4];
            #pragma unroll
            for (int ii = 0; ii < 4; ii++) acc[ii] = 0ull;
            const float* xr  = &xrn[j * XS];
            const float* xlb = &xln[i0 * XS];
            #pragma unroll 2
            for (int c = 0; c < 64; c += 4) {
                ulonglong2 r0 = ld4(xr + c);
                ulonglong2 a2 = ld4(att04S + c);
                #pragma unroll
                for (int ii = 0; ii < 4; ii++) {
                    ulonglong2 xl4 = ld4(xlb + ii * XS + c);
                    acc[ii] = fma2(abs2(add2(xl4.x, r0.x)), a2.x, acc[ii]);
                    acc[ii] = fma2(abs2(add2(xl4.y, r0.y)), a2.y, acc[ii]);
                }
            }
            float sr = SRa[j];
            #pragma unroll
            for (int ii = 0; ii < 4; ii++) {
                int i = i0 + ii;
                float2 t = unp2(acc[ii]);
                float e = 0.6f * (SLa[i] + sr) + (t.x + t.y);
                bool ok = (i == j) || (impS[i] != 0.f && impj != 0.f);
                eBuf[i * 64 + j] = ok ? e : NEGV;
            }
        }
    }
    __syncthreads();

    // ---- softmax stage 1: partial max per half-column ----
    if (tid < 128 * H) {
        int unit = tid & (64 * H - 1);
        int half = tid >= 64 * H;
        int j = unit & 63, h = unit >> 6;
        const float* col = eBuf + h * 4096 + half * 2048 + j;
        float m0 = col[0], m1 = col[64];
        #pragma unroll 5
        for (int i = 2; i < 32; i += 2) {
            m0 = fmaxf(m0, col[i * 64]);
            m1 = fmaxf(m1, col[(i + 1) * 64]);
        }
        scratch[tid] = fmaxf(m0, m1);
    }
    __syncthreads();

    // ---- softmax stage 2: exp + partial sum per half-column ----
    if (tid < 128 * H) {
        int unit = tid & (64 * H - 1);
        int half = tid >= 64 * H;
        int j = unit & 63, h = unit >> 6;
        float mx = fmaxf(scratch[unit], scratch[unit + 64 * H]);
        float* col = eBuf + h * 4096 + half * 2048 + j;
        float s0 = 0.f, s1 = 0.f;
        #pragma unroll 5
        for (int i = 0; i < 32; i += 2) {
            float p0 = __expf(col[i * 64] - mx);
            float p1 = __expf(col[(i + 1) * 64] - mx);
            col[i * 64] = p0;
            col[(i + 1) * 64] = p1;
            s0 += p0; s1 += p1;
        }
        scratch[512 + tid] = s0 + s1;   // ps[half*64H + h*64 + j]
    }
    __syncthreads();

    // ---- aggregate: out[j][f] = inv_j * sum_i p_ij * xl_i[f] + bias ----
    if constexpr (!FINAL) {
        int l = tid & 31, w = tid >> 5;
        int fb = 8 * (w & 15);          // f-octet (never crosses an h boundary)
        int jb = 32 * (w >> 4);         // j-half
        int h  = fb >> 5;
        int j  = jb + l;
        const float* pcol = eBuf + h * 4096;
        u64 a[4];
        #pragma unroll
        for (int q = 0; q < 4; q++) a[q] = 0ull;
        #pragma unroll 2
        for (int i = 0; i < 64; i++) {
            const float* xli = &xln[i * XS + fb];
            ulonglong2 xA = ld4(xli);        // broadcast
            ulonglong2 xB = ld4(xli + 4);    // broadcast
            u64 pv = dup2(pcol[i * 64 + j]); // coalesced
            a[0] = fma2(xA.x, pv, a[0]); a[1] = fma2(xA.y, pv, a[1]);
            a[2] = fma2(xB.x, pv, a[2]); a[3] = fma2(xB.y, pv, a[3]);
        }
        float inv = 1.f / (scratch[512 + h * 64 + j] + scratch[512 + 256 + h * 64 + j]);
        #pragma unroll
        for (int q = 0; q < 4; q++) {
            float2 v = unp2(a[q]);
            int f = fb + 2 * q;
            hT[f * HTS + j]       = fmaf(v.x, inv, biasS[f]);
            hT[(f + 1) * HTS + j] = fmaf(v.y, inv, biasS[f + 1]);
        }
        __syncthreads();
        // ---- LayerNorm (biased var, eps 1e-5) + ReLU over hT columns ----
        {
            float g0 = lng[l], g1 = lng[l + 32], g2 = lng[l + 64], g3 = lng[l + 96];
            float bb0 = lnb[l], bb1 = lnb[l + 32], bb2 = lnb[l + 64], bb3 = lnb[l + 96];
            #pragma unroll
            for (int t = 0; t < 2; t++) {
                int m = w + 32 * t;
                float x0 = hT[l * HTS + m],        x1 = hT[(l + 32) * HTS + m];
                float x2 = hT[(l + 64) * HTS + m], x3 = hT[(l + 96) * HTS + m];
                float s = x0 + x1 + x2 + x3;
                #pragma unroll
                for (int off = 16; off; off >>= 1) s += __shfl_xor_sync(~0u, s, off);
                float mean = s * (1.f / 128.f);
                float d0 = x0 - mean, d1 = x1 - mean, d2 = x2 - mean, d3 = x3 - mean;
                float qv = d0 * d0 + d1 * d1 + d2 * d2 + d3 * d3;
                #pragma unroll
                for (int off = 16; off; off >>= 1) qv += __shfl_xor_sync(~0u, qv, off);
                float rstd = rsqrtf(qv * (1.f / 128.f) + 1e-5f);
                hT[l * HTS + m]        = fmaxf(fmaf(d0 * rstd, g0, bb0), 0.f);
                hT[(l + 32) * HTS + m] = fmaxf(fmaf(d1 * rstd, g1, bb1), 0.f);
                hT[(l + 64) * HTS + m] = fmaxf(fmaf(d2 * rstd, g2, bb2), 0.f);
                hT[(l + 96) * HTS + m] = fmaxf(fmaf(d3 * rstd, g3, bb3), 0.f);
            }
        }
        __syncthreads();
    } else {
        // final layer: Fout=64, H=1 — 2 j per warp, coalesced float2 gmem store
        int l = tid & 31, w = tid >> 5;
        #pragma unroll
        for (int jj = 0; jj < 2; jj++) {
            int j = w * 2 + jj;
            const float* pcol = eBuf + j;
            u64 acc = 0ull;
            #pragma unroll 4
            for (int i = 0; i < 64; i++)
                acc = fma2(ld2(&xln[i * XS + 2 * l]), dup2(pcol[i * 64]), acc);
            float inv = 1.f / (scratch[512 + j] + scratch[512 + 64 + j]);
            float2 v = unp2(acc);
            float2 r;
            r.x = fmaf(v.x, inv, biasS[2 * l]);
            r.y = fmaf(v.y, inv, biasS[2 * l + 1]);
            *reinterpret_cast<float2*>(&outg[(b * 64 + j) * 64 + 2 * l]) = r;
        }
    }
}

__global__ __launch_bounds__(1024, 1)
void GNN_kernel(const float* __restrict__ team_obs,
                const float* __restrict__ target_obs,
                const float* __restrict__ team_mask,
                const float* __restrict__ ltm,
                const float* __restrict__ W_emb,
                const float* __restrict__ b_emb,
                const float* __restrict__ Wl1, const float* __restrict__ Wr1,
                const float* __restrict__ att1, const float* __restrict__ b1,
                const float* __restrict__ Wl2, const float* __restrict__ Wr2,
                const float* __restrict__ att2, const float* __restrict__ b2,
                const float* __restrict__ Wl3, const float* __restrict__ Wr3,
                const float* __restrict__ att3, const float* __restrict__ b3,
                const float* __restrict__ ln1g, const float* __restrict__ ln1b,
                const float* __restrict__ ln2g, const float* __restrict__ ln2b,
                float* __restrict__ outg)
{
    extern __shared__ float sm[];
    float* hT     = sm;                // 128*68 = 8704
    float* xln    = hT + 8704;         // 64*132 = 8448
    float* xrn    = xln + 8448;        // 8448
    float* eBuf   = xrn + 8448;        // 16384 (layout [h][i][j])
    float* SLa    = eBuf + 16384;      // 256  ([h*64+i])
    float* SRa    = SLa + 256;         // 256
    float* attS   = SRa + 256;         // 128
    float* att04S = attS + 128;        // 128
    float* biasS  = att04S + 128;      // 128
    float* finS   = biasS + 128;       // 1024 (fin, then softmax pm/ps scratch)
    float* impS   = finS + 1024;       // 64
    // total 43968 floats = 175872 B

    const int tid = threadIdx.x;
    const int b   = blockIdx.x;

    // ---------------- Phase 0: build fin (64x16) + importance flags ----------------
    if (tid < 64) {
        float ok;
        if (tid < 16) ok = (team_mask[b * 32 + tid] != NEGV) ? 1.0f : 0.0f;
        else          ok = (ltm[b * 49 + (tid - 16)] != 0.0f) ? 1.0f : 0.0f;
        impS[tid] = ok;
    }
    {
        int m = tid >> 4, k = tid & 15;
        float v = 0.0f;
        if (m < 16) {
            if (k < 14) v = team_obs[(b * 16 + m) * 14 + k];
        } else {
            int t = m - 16;
            const float* src = &target_obs[(b * 48 + t) * 15];
            if (k < 12)       v = src[k];
            else if (k == 14) v = src[12];
            else if (k == 15) v = src[13];
        }
        finS[tid] = v;
    }
    __syncthreads();

    // ---------------- Phase 1: embedding h = fin @ W_emb + b_emb -> hT (transposed) ----------------
    {
        int f = tid & 127, g = tid >> 7;   // g in 0..7
        float wc[16];
        #pragma unroll
        for (int k = 0; k < 16; k++) wc[k] = W_emb[k * 128 + f];
        float bb = b_emb[f];
        #pragma unroll 4
        for (int t = 0; t < 8; t++) {
            int m = g + 8 * t;
            float acc = bb;
            const float* fr = &finS[m * 16];
            #pragma unroll
            for (int k = 0; k < 16; k++) acc = fmaf(fr[k], wc[k], acc);
            hT[f * HTS + m] = acc;
        }
    }
    __syncthreads();

    layer_body<128, 4, false>(hT, xln, xrn, eBuf, SLa, SRa, attS, att04S, biasS, finS, impS,
                              Wl1, Wr1, att1, b1, ln1g, ln1b, nullptr, b, tid);
    layer_body<128, 4, false>(hT, xln, xrn, eBuf, SLa, SRa, attS, att04S, biasS, finS, impS,
                              Wl2, Wr2, att2, b2, ln2g, ln2b, nullptr, b, tid);
    layer_body<64, 1, true>(hT, xln, xrn, eBuf, SLa, SRa, attS, att04S, biasS, finS, impS,
                            Wl3, Wr3, att3, b3, nullptr, nullptr, outg, b, tid);
}

extern "C" void kernel_launch(void* const* d_in, const int* in_sizes, int n_in,
                              void* d_out, int out_size) {
    (void)in_sizes; (void)n_in; (void)out_size;
    const size_t smem = 43968u * sizeof(float);
    cudaFuncSetAttribute(GNN_kernel, cudaFuncAttributeMaxDynamicSharedMemorySize, (int)smem);
    GNN_kernel<<<128, 1024, smem>>>(
        (const float*)d_in[0],  (const float*)d_in[1],  (const float*)d_in[2],
        (const float*)d_in[3],  (const float*)d_in[4],  (const float*)d_in[5],
        (const float*)d_in[6],  (const float*)d_in[7],  (const float*)d_in[8],
        (const float*)d_in[9],  (const float*)d_in[10], (const float*)d_in[11],
        (const float*)d_in[12], (const float*)d_in[13], (const float*)d_in[14],
        (const float*)d_in[15], (const float*)d_in[16], (const float*)d_in[17],
        (const float*)d_in[18], (const float*)d_in[19], (const float*)d_in[20],
        (const float*)d_in[21], (float*)d_out);
}

// round 17
// speedup vs baseline: 1.1565x; 1.1565x over previous
#include <cuda_runtime.h>

#define NEGV (-1000000000.0f)
#define HTS 68    // hT row stride (transposed h: hT[k][m]); mult of 4 => 16B-aligned row quads
#define XS  132   // xl/xr row stride; mult of 4, stride%32==4 => conflict-free lane-strided LDS.128

typedef unsigned long long u64;

__device__ __forceinline__ u64 ld2(const float* p) {
    return *reinterpret_cast<const u64*>(p);
}
__device__ __forceinline__ ulonglong2 ld4(const float* p) {
    return *reinterpret_cast<const ulonglong2*>(p);
}
__device__ __forceinline__ u64 fma2(u64 a, u64 b, u64 c) {
    u64 d; asm("fma.rn.f32x2 %0,%1,%2,%3;" : "=l"(d) : "l"(a), "l"(b), "l"(c)); return d;
}
__device__ __forceinline__ u64 add2(u64 a, u64 b) {
    u64 d; asm("add.rn.f32x2 %0,%1,%2;" : "=l"(d) : "l"(a), "l"(b)); return d;
}
__device__ __forceinline__ u64 abs2(u64 a) {
    return a & 0x7FFFFFFF7FFFFFFFull;
}
__device__ __forceinline__ u64 dup2(float x) {
    u64 d; asm("mov.b64 %0,{%1,%1};" : "=l"(d) : "f"(x)); return d;
}
__device__ __forceinline__ float2 unp2(u64 a) {
    float2 r; asm("mov.b64 {%0,%1},%2;" : "=f"(r.x), "=f"(r.y) : "l"(a)); return r;
}

template<int Fout, int H, bool FINAL>
__device__ __forceinline__ void layer_body(
    float* __restrict__ hT, float* __restrict__ xln, float* __restrict__ xrn,
    float* __restrict__ eBuf, float* __restrict__ SLa, float* __restrict__ SRa,
    float* __restrict__ attS, float* __restrict__ att04S, float* __restrict__ biasS,
    float* __restrict__ invS, const float* __restrict__ impS,
    const float* __restrict__ Wl, const float* __restrict__ Wr,
    const float* __restrict__ att, const float* __restrict__ bias,
    const float* __restrict__ lng, const float* __restrict__ lnb,
    float* __restrict__ outg, int b, int tid)
{
    constexpr int C = Fout / H;

    // ---- stage att / 0.4*att / bias (read only after next sync) ----
    if (tid < Fout) {
        float a = att[tid];
        attS[tid] = a; att04S[tid] = 0.4f * a; biasS[tid] = bias[tid];
    }

    // ---- dual GEMM: xl = h @ Wl, xr = h @ Wr (4 f per thread, W via LDG.128, hT row-quad bcast) ----
    {
        constexpr int NFS   = Fout / 4;       // f-quad slots per matrix: 32 or 16
        constexpr int nGrp  = 512 / NFS;      // 16 or 32
        constexpr int halfG = nGrp / 2;       // 8 or 16
        constexpr int rows  = 64 / halfG;     // 8 or 4
        constexpr int RP    = rows / 2;       // 4 or 2
        constexpr int RQ    = rows / 4;       // 2 or 1
        int fslot = tid % NFS;
        int grp   = tid / NFS;
        bool matSel = grp >= halfG;
        int sub     = matSel ? grp - halfG : grp;
        int rstart  = sub * rows;
        const float* W = matSel ? Wr : Wl;
        float* dst     = matSel ? xrn : xln;
        int f0 = 4 * fslot;
        u64 accA[RP], accB[RP], accC[RP], accD[RP];
        #pragma unroll
        for (int p = 0; p < RP; p++) { accA[p] = 0ull; accB[p] = 0ull; accC[p] = 0ull; accD[p] = 0ull; }
        #pragma unroll 1
        for (int kk = 0; kk < 128; kk += 8) {
            ulonglong2 wq[8];
            #pragma unroll
            for (int q = 0; q < 8; q++)
                wq[q] = ld4(&W[(kk + q) * Fout + f0]);   // LDG.128, coalesced
            #pragma unroll
            for (int q = 0; q < 8; q++) {
                float2 wab = unp2(wq[q].x), wcd = unp2(wq[q].y);
                u64 wa = dup2(wab.x), wb = dup2(wab.y);
                u64 wc = dup2(wcd.x), wd = dup2(wcd.y);
                const float* hk = &hT[(kk + q) * HTS + rstart];
                #pragma unroll
                for (int r = 0; r < RQ; r++) {
                    ulonglong2 h4 = ld4(hk + 4 * r);     // broadcast
                    accA[2*r]   = fma2(h4.x, wa, accA[2*r]);
                    accA[2*r+1] = fma2(h4.y, wa, accA[2*r+1]);
                    accB[2*r]   = fma2(h4.x, wb, accB[2*r]);
                    accB[2*r+1] = fma2(h4.y, wb, accB[2*r+1]);
                    accC[2*r]   = fma2(h4.x, wc, accC[2*r]);
                    accC[2*r+1] = fma2(h4.y, wc, accC[2*r+1]);
                    accD[2*r]   = fma2(h4.x, wd, accD[2*r]);
                    accD[2*r+1] = fma2(h4.y, wd, accD[2*r+1]);
                }
            }
        }
        #pragma unroll
        for (int p = 0; p < RP; p++) {
            float2 vA = unp2(accA[p]), vB = unp2(accB[p]);
            float2 vC = unp2(accC[p]), vD = unp2(accD[p]);
            int r = rstart + 2 * p;
            float4 s0; s0.x = vA.x; s0.y = vB.x; s0.z = vC.x; s0.w = vD.x;
            float4 s1; s1.x = vA.y; s1.y = vB.y; s1.z = vC.y; s1.w = vD.y;
            *reinterpret_cast<float4*>(&dst[r * XS + f0])       = s0;   // STS.128
            *reinterpret_cast<float4*>(&dst[(r + 1) * XS + f0]) = s1;
        }
    }
    __syncthreads();

    // ---- SL_i[h] = sum_c xl*att ; SR_j[h] = sum_c xr*att ----
    if (tid < 128 * H) {
        int i   = tid & 63;
        int hm  = tid >> 6;
        int h   = hm & (H - 1);
        int mat = hm / H;
        const float* x = (mat ? xrn : xln) + i * XS + h * C;
        const float* a = attS + h * C;
        u64 acc = 0ull;
        #pragma unroll
        for (int c = 0; c < C; c += 4) {
            ulonglong2 x4 = ld4(x + c);
            ulonglong2 a4 = ld4(a + c);
            acc = fma2(x4.x, a4.x, acc);
            acc = fma2(x4.y, a4.y, acc);
        }
        float2 v = unp2(acc);
        (mat ? SRa : SLa)[h * 64 + i] = v.x + v.y;
    }
    __syncthreads();

    // ---- e-phase: e_ij = 0.6*(SL_i+SR_j) + sum_c |xl+xr| * (0.4*att); mask folded ----
    {
        int l = tid & 31, w = tid >> 5;           // 16 warps
        if constexpr (!FINAL) {
            // (i-oct x h-pair) per warp: 8 octs x 2 h-pairs = 16 warps
            int i0 = (w & 7) * 8;
            int h0 = (w >> 3) * 2;
            float impj0 = impS[l], impj1 = impS[l + 32];
            #pragma unroll 1
            for (int hh = 0; hh < 2; hh++) {
                int h = h0 + hh;
                u64 acc[8][2];
                #pragma unroll
                for (int ii = 0; ii < 8; ii++) { acc[ii][0] = 0ull; acc[ii][1] = 0ull; }
                const float* a04 = att04S + h * C;
                const float* xr0 = &xrn[l * XS + h * C];
                const float* xr1 = &xrn[(l + 32) * XS + h * C];
                const float* xlb = &xln[i0 * XS + h * C];
                #pragma unroll 1
                for (int c = 0; c < C; c += 4) {
                    ulonglong2 r0 = ld4(xr0 + c);
                    ulonglong2 r1 = ld4(xr1 + c);
                    ulonglong2 a2 = ld4(a04 + c);
                    #pragma unroll
                    for (int ii = 0; ii < 8; ii++) {
                        ulonglong2 xl4 = ld4(xlb + ii * XS + c);   // broadcast
                        acc[ii][0] = fma2(abs2(add2(xl4.x, r0.x)), a2.x, acc[ii][0]);
                        acc[ii][0] = fma2(abs2(add2(xl4.y, r0.y)), a2.y, acc[ii][0]);
                        acc[ii][1] = fma2(abs2(add2(xl4.x, r1.x)), a2.x, acc[ii][1]);
                        acc[ii][1] = fma2(abs2(add2(xl4.y, r1.y)), a2.y, acc[ii][1]);
                    }
                }
                float sr0 = SRa[h * 64 + l], sr1 = SRa[h * 64 + l + 32];
                #pragma unroll
                for (int ii = 0; ii < 8; ii++) {
                    int i = i0 + ii;
                    float impi = impS[i];
                    float sl = SLa[h * 64 + i];
                    float2 t0 = unp2(acc[ii][0]), t1 = unp2(acc[ii][1]);
                    float e0 = 0.6f * (sl + sr0) + (t0.x + t0.y);
                    float e1 = 0.6f * (sl + sr1) + (t1.x + t1.y);
                    bool ok0 = (i == l)      || (impi != 0.f && impj0 != 0.f);
                    bool ok1 = (i == l + 32) || (impi != 0.f && impj1 != 0.f);
                    eBuf[h * 4096 + i * 64 + l]      = ok0 ? e0 : NEGV;
                    eBuf[h * 4096 + i * 64 + l + 32] = ok1 ? e1 : NEGV;
                }
            }
        } else {
            // H=1, C=64: (i-oct x j-half) per warp
            int i0 = (w & 7) * 8;
            int jb = (w >> 3) * 32;
            int j  = jb + l;
            float impj = impS[j];
            u64 acc[8];
            #pragma unroll
            for (int ii = 0; ii < 8; ii++) acc[ii] = 0ull;
            const float* xr  = &xrn[j * XS];
            const float* xlb = &xln[i0 * XS];
            #pragma unroll 1
            for (int c = 0; c < 64; c += 4) {
                ulonglong2 r0 = ld4(xr + c);
                ulonglong2 a2 = ld4(att04S + c);
                #pragma unroll
                for (int ii = 0; ii < 8; ii++) {
                    ulonglong2 xl4 = ld4(xlb + ii * XS + c);
                    acc[ii] = fma2(abs2(add2(xl4.x, r0.x)), a2.x, acc[ii]);
                    acc[ii] = fma2(abs2(add2(xl4.y, r0.y)), a2.y, acc[ii]);
                }
            }
            float sr = SRa[j];
            #pragma unroll
            for (int ii = 0; ii < 8; ii++) {
                int i = i0 + ii;
                float2 t = unp2(acc[ii]);
                float e = 0.6f * (SLa[i] + sr) + (t.x + t.y);
                bool ok = (i == j) || (impS[i] != 0.f && impj != 0.f);
                eBuf[i * 64 + j] = ok ? e : NEGV;
            }
        }
    }
    __syncthreads();

    // ---- softmax over i per (j,h); two independent chains for ILP ----
    if (tid < 64 * H) {
        int j = tid & 63, h = tid >> 6;
        float* col = eBuf + h * 4096 + j;
        float m0 = col[0], m1 = col[64];
        #pragma unroll 8
        for (int i = 2; i < 64; i += 2) {
            m0 = fmaxf(m0, col[i * 64]);
            m1 = fmaxf(m1, col[(i + 1) * 64]);
        }
        float mx = fmaxf(m0, m1);
        float s0 = 0.f, s1 = 0.f;
        #pragma unroll 8
        for (int i = 0; i < 64; i += 2) {
            float p0 = __expf(col[i * 64] - mx);
            float p1 = __expf(col[(i + 1) * 64] - mx);
            col[i * 64] = p0;
            col[(i + 1) * 64] = p1;
            s0 += p0; s1 += p1;
        }
        invS[h * 64 + j] = 1.f / (s0 + s1);
    }
    __syncthreads();

    // ---- aggregate: out[j][f] = inv_j * sum_i p_ij * xl_i[f] + bias ----
    if constexpr (!FINAL) {
        int l = tid & 31, w = tid >> 5;
        int fb = 8 * w;            // 8 f's per warp; octet never crosses an h boundary
        int h  = w >> 2;
        const float* pcol = eBuf + h * 4096;
        u64 a0[4], a1[4];
        #pragma unroll
        for (int q = 0; q < 4; q++) { a0[q] = 0ull; a1[q] = 0ull; }
        #pragma unroll 2
        for (int i = 0; i < 64; i++) {
            const float* xli = &xln[i * XS + fb];
            ulonglong2 xA = ld4(xli);        // broadcast
            ulonglong2 xB = ld4(xli + 4);    // broadcast
            u64 pa = dup2(pcol[i * 64 + l]);
            u64 pb = dup2(pcol[i * 64 + l + 32]);
            a0[0] = fma2(xA.x, pa, a0[0]); a0[1] = fma2(xA.y, pa, a0[1]);
            a0[2] = fma2(xB.x, pa, a0[2]); a0[3] = fma2(xB.y, pa, a0[3]);
            a1[0] = fma2(xA.x, pb, a1[0]); a1[1] = fma2(xA.y, pb, a1[1]);
            a1[2] = fma2(xB.x, pb, a1[2]); a1[3] = fma2(xB.y, pb, a1[3]);
        }
        float inv0 = invS[h * 64 + l], inv1 = invS[h * 64 + l + 32];
        #pragma unroll
        for (int q = 0; q < 4; q++) {
            float2 v0 = unp2(a0[q]), v1 = unp2(a1[q]);
            int f = fb + 2 * q;
            hT[f * HTS + l]            = fmaf(v0.x, inv0, biasS[f]);
            hT[(f + 1) * HTS + l]      = fmaf(v0.y, inv0, biasS[f + 1]);
            hT[f * HTS + l + 32]       = fmaf(v1.x, inv1, biasS[f]);
            hT[(f + 1) * HTS + l + 32] = fmaf(v1.y, inv1, biasS[f + 1]);
        }
        __syncthreads();
        // ---- LayerNorm (biased var, eps 1e-5) + ReLU over hT columns ----
        {
            float g0 = lng[l], g1 = lng[l + 32], g2 = lng[l + 64], g3 = lng[l + 96];
            float bb0 = lnb[l], bb1 = lnb[l + 32], bb2 = lnb[l + 64], bb3 = lnb[l + 96];
            #pragma unroll
            for (int t = 0; t < 4; t++) {
                int m = w * 4 + t;
                float x0 = hT[l * HTS + m],        x1 = hT[(l + 32) * HTS + m];
                float x2 = hT[(l + 64) * HTS + m], x3 = hT[(l + 96) * HTS + m];
                float s = x0 + x1 + x2 + x3;
                #pragma unroll
                for (int off = 16; off; off >>= 1) s += __shfl_xor_sync(~0u, s, off);
                float mean = s * (1.f / 128.f);
                float d0 = x0 - mean, d1 = x1 - mean, d2 = x2 - mean, d3 = x3 - mean;
                float qv = d0 * d0 + d1 * d1 + d2 * d2 + d3 * d3;
                #pragma unroll
                for (int off = 16; off; off >>= 1) qv += __shfl_xor_sync(~0u, qv, off);
                float rstd = rsqrtf(qv * (1.f / 128.f) + 1e-5f);
                hT[l * HTS + m]        = fmaxf(fmaf(d0 * rstd, g0, bb0), 0.f);
                hT[(l + 32) * HTS + m] = fmaxf(fmaf(d1 * rstd, g1, bb1), 0.f);
                hT[(l + 64) * HTS + m] = fmaxf(fmaf(d2 * rstd, g2, bb2), 0.f);
                hT[(l + 96) * HTS + m] = fmaxf(fmaf(d3 * rstd, g3, bb3), 0.f);
            }
        }
        __syncthreads();
    } else {
        // final layer: Fout=64, H=1 — coalesced gmem store (lanes along f)
        int l = tid & 31, w = tid >> 5;
        #pragma unroll
        for (int jj = 0; jj < 4; jj++) {
            int j = w + 16 * jj;
            const float* pcol = eBuf + j;
            u64 acc = 0ull;
            #pragma unroll 4
            for (int i = 0; i < 64; i++)
                acc = fma2(ld2(&xln[i * XS + 2 * l]), dup2(pcol[i * 64]), acc);
            float inv = invS[j];
            float2 v = unp2(acc);
            float2 r;
            r.x = fmaf(v.x, inv, biasS[2 * l]);
            r.y = fmaf(v.y, inv, biasS[2 * l + 1]);
            *reinterpret_cast<float2*>(&outg[(b * 64 + j) * 64 + 2 * l]) = r;
        }
    }
}

__global__ __launch_bounds__(512, 1)
void GNN_kernel(const float* __restrict__ team_obs,
                const float* __restrict__ target_obs,
                const float* __restrict__ team_mask,
                const float* __restrict__ ltm,
                const float* __restrict__ W_emb,
                const float* __restrict__ b_emb,
                const float* __restrict__ Wl1, const float* __restrict__ Wr1,
                const float* __restrict__ att1, const float* __restrict__ b1,
                const float* __restrict__ Wl2, const float* __restrict__ Wr2,
                const float* __restrict__ att2, const float* __restrict__ b2,
                const float* __restrict__ Wl3, const float* __restrict__ Wr3,
                const float* __restrict__ att3, const float* __restrict__ b3,
                const float* __restrict__ ln1g, const float* __restrict__ ln1b,
                const float* __restrict__ ln2g, const float* __restrict__ ln2b,
                float* __restrict__ outg)
{
    extern __shared__ float sm[];
    float* hT     = sm;                // 128*68 = 8704
    float* xln    = hT + 8704;         // 64*132 = 8448
    float* xrn    = xln + 8448;        // 8448
    float* eBuf   = xrn + 8448;        // 16384 (layout [h][i][j])
    float* SLa    = eBuf + 16384;      // 256  ([h*64+i])
    float* SRa    = SLa + 256;         // 256
    float* attS   = SRa + 256;         // 128
    float* att04S = attS + 128;        // 128
    float* biasS  = att04S + 128;      // 128
    float* invS   = biasS + 128;       // 256  ([h*64+j])
    float* finS   = invS + 256;        // 1024
    float* impS   = finS + 1024;       // 64
    // total 44224 floats = 176896 B

    const int tid = threadIdx.x;
    const int b   = blockIdx.x;

    // ---------------- Phase 0: build fin (64x16) + importance flags ----------------
    if (tid < 64) {
        float ok;
        if (tid < 16) ok = (team_mask[b * 32 + tid] != NEGV) ? 1.0f : 0.0f;
        else          ok = (ltm[b * 49 + (tid - 16)] != 0.0f) ? 1.0f : 0.0f;
        impS[tid] = ok;
    }
    for (int idx = tid; idx < 1024; idx += 512) {
        int m = idx >> 4, k = idx & 15;
        float v = 0.0f;
        if (m < 16) {
            if (k < 14) v = team_obs[(b * 16 + m) * 14 + k];
        } else {
            int t = m - 16;
            const float* src = &target_obs[(b * 48 + t) * 15];
            if (k < 12)       v = src[k];
            else if (k == 14) v = src[12];
            else if (k == 15) v = src[13];
        }
        finS[idx] = v;
    }
    __syncthreads();

    // ---------------- Phase 1: embedding h = fin @ W_emb + b_emb -> hT (transposed) ----------------
    {
        int f = tid & 127, g = tid >> 7;
        float wc[16];
        #pragma unroll
        for (int k = 0; k < 16; k++) wc[k] = W_emb[k * 128 + f];
        float bb = b_emb[f];
        #pragma unroll 4
        for (int t = 0; t < 16; t++) {
            int m = g + 4 * t;
            float acc = bb;
            const float* fr = &finS[m * 16];
            #pragma unroll
            for (int k = 0; k < 16; k++) acc = fmaf(fr[k], wc[k], acc);
            hT[f * HTS + m] = acc;
        }
    }
    __syncthreads();

    layer_body<128, 4, false>(hT, xln, xrn, eBuf, SLa, SRa, attS, att04S, biasS, invS, impS,
                              Wl1, Wr1, att1, b1, ln1g, ln1b, nullptr, b, tid);
    layer_body<128, 4, false>(hT, xln, xrn, eBuf, SLa, SRa, attS, att04S, biasS, invS, impS,
                              Wl2, Wr2, att2, b2, ln2g, ln2b, nullptr, b, tid);
    layer_body<64, 1, true>(hT, xln, xrn, eBuf, SLa, SRa, attS, att04S, biasS, invS, impS,
                            Wl3, Wr3, att3, b3, nullptr, nullptr, outg, b, tid);
}

extern "C" void kernel_launch(void* const* d_in, const int* in_sizes, int n_in,
                              void* d_out, int out_size) {
    (void)in_sizes; (void)n_in; (void)out_size;
    const size_t smem = 44224u * sizeof(float);
    cudaFuncSetAttribute(GNN_kernel, cudaFuncAttributeMaxDynamicSharedMemorySize, (int)smem);
    GNN_kernel<<<128, 512, smem>>>(
        (const float*)d_in[0],  (const float*)d_in[1],  (const float*)d_in[2],
        (const float*)d_in[3],  (const float*)d_in[4],  (const float*)d_in[5],
        (const float*)d_in[6],  (const float*)d_in[7],  (const float*)d_in[8],
        (const float*)d_in[9],  (const float*)d_in[10], (const float*)d_in[11],
        (const float*)d_in[12], (const float*)d_in[13], (const float*)d_in[14],
        (const float*)d_in[15], (const float*)d_in[16], (const float*)d_in[17],
        (const float*)d_in[18], (const float*)d_in[19], (const float*)d_in[20],
        (const float*)d_in[21], (float*)d_out);
}